// round 4
// baseline (speedup 1.0000x reference)
#include <cuda_runtime.h>

#define DIMS 128
#define NLAB 5
#define MAXN 50000

// ---------------- device scratch (no allocations allowed) ----------------
__device__ float g_W2[2][DIMS * DIMS];      // W_in@W_in, W_out@W_out
__device__ float g_c[2][NLAB];              // per-label gate constants
__device__ float g_gate[2][MAXN];           // per-node h.Wg scalars
__device__ float g_hl[MAXN * DIMS];         // x @ W_loop
__device__ float g_hin[MAXN * DIMS];        // x @ (W_in @ W_in)
__device__ float g_hout[MAXN * DIMS];       // x @ (W_out @ W_out)
__device__ float g_acc[MAXN * DIMS];        // accumulator (xl + scatter sums)

__device__ __forceinline__ float sigmoidf_(float x) {
    return 1.0f / (1.0f + __expf(-x));
}

__device__ __forceinline__ float warp_sum(float v) {
#pragma unroll
    for (int o = 16; o > 0; o >>= 1) v += __shfl_xor_sync(0xffffffffu, v, o);
    return v;
}

// ---------------- prep: W2 = W @ W (tiny) ----------------
__global__ void prep_w2_kernel(const float* __restrict__ Win,
                               const float* __restrict__ Wout) {
    __shared__ float wrow[DIMS];
    const float* W = (blockIdx.y == 0) ? Win : Wout;
    int r = blockIdx.x, c = threadIdx.x;
    wrow[c] = W[r * DIMS + c];
    __syncthreads();
    float s = 0.0f;
#pragma unroll 8
    for (int k = 0; k < DIMS; k++) s += wrow[k] * W[k * DIMS + c];
    g_W2[blockIdx.y][r * DIMS + c] = s;
}

// ---------------- prep: c[dir][lab] = b_lab[lab] . Wg + bg_lab[lab] ----------------
__global__ void prep_c_kernel(const float* __restrict__ Wg_in,
                              const float* __restrict__ blab_in,
                              const float* __restrict__ bg_in,
                              const float* __restrict__ Wg_out,
                              const float* __restrict__ blab_out,
                              const float* __restrict__ bg_out) {
    int t = threadIdx.x;
    if (t >= 2 * NLAB) return;
    int w = t / NLAB, l = t % NLAB;
    const float* Wg = w ? Wg_out : Wg_in;
    const float* bl = w ? blab_out : blab_in;
    const float* bg = w ? bg_out : bg_in;
    float s = bg[l];
    for (int d = 0; d < DIMS; d++) s += bl[l * DIMS + d] * Wg[d];
    g_c[w][l] = s;
}

// ---------------- SGEMM: C[M,128] = x[M,128] @ W[128,128] ----------------
// blockIdx.y: 0 -> W_loop/g_hl, 1 -> W2_in/g_hin, 2 -> W2_out/g_hout
__global__ __launch_bounds__(256) void gemm_kernel(const float* __restrict__ x,
                                                   const float* __restrict__ Wloop,
                                                   int M) {
    extern __shared__ float smem[];
    float* As = smem;                 // [128][132] padded rows
    float* Bs = smem + 128 * 132;     // [128][128]

    const float* W = (blockIdx.y == 0) ? Wloop : g_W2[blockIdx.y - 1];
    float* outp = (blockIdx.y == 0) ? g_hl : ((blockIdx.y == 1) ? g_hin : g_hout);

    int tid = threadIdx.x;
    int m0 = blockIdx.x * 128;

    float4* Bs4 = (float4*)Bs;
    const float4* W4 = (const float4*)W;
#pragma unroll
    for (int i = 0; i < 16; i++) Bs4[i * 256 + tid] = W4[i * 256 + tid];

    float4* As4 = (float4*)As;
    const float4* x4 = (const float4*)x;
#pragma unroll
    for (int i = 0; i < 16; i++) {
        int fidx = tid + i * 256;
        int m = fidx >> 5, kq = fidx & 31;
        float4 v = make_float4(0.f, 0.f, 0.f, 0.f);
        if (m0 + m < M) v = x4[(size_t)(m0 + m) * 32 + kq];
        As4[m * 33 + kq] = v;
    }
    __syncthreads();

    int tx = tid & 15, ty = tid >> 4;
    float acc[8][8];
#pragma unroll
    for (int i = 0; i < 8; i++)
#pragma unroll
        for (int j = 0; j < 8; j++) acc[i][j] = 0.0f;

    const float* arow = As + (ty * 8) * 132;
#pragma unroll 2
    for (int k = 0; k < 128; k++) {
        float a[8];
#pragma unroll
        for (int i = 0; i < 8; i++) a[i] = arow[i * 132 + k];
        float4 b0 = Bs4[k * 32 + tx * 2];
        float4 b1 = Bs4[k * 32 + tx * 2 + 1];
        float b[8] = {b0.x, b0.y, b0.z, b0.w, b1.x, b1.y, b1.z, b1.w};
#pragma unroll
        for (int i = 0; i < 8; i++)
#pragma unroll
            for (int j = 0; j < 8; j++) acc[i][j] += a[i] * b[j];
    }

#pragma unroll
    for (int i = 0; i < 8; i++) {
        int row = m0 + ty * 8 + i;
        if (row < M) {
            float4* o4 = (float4*)(outp + (size_t)row * 128 + tx * 8);
            o4[0] = make_float4(acc[i][0], acc[i][1], acc[i][2], acc[i][3]);
            o4[1] = make_float4(acc[i][4], acc[i][5], acc[i][6], acc[i][7]);
        }
    }
}

// ---------------- node post: xl gating into g_acc; per-node gate dot scalars ----------------
__global__ void node_post_kernel(const float* __restrict__ b_loop,
                                 const float* __restrict__ Wg_loop,
                                 const float* __restrict__ bg_loop,
                                 const float* __restrict__ Wg_in,
                                 const float* __restrict__ Wg_out, int N) {
    int gw = (blockIdx.x * blockDim.x + threadIdx.x) >> 5;
    int lane = threadIdx.x & 31;
    if (gw >= N) return;

    float4 xl = ((const float4*)g_hl)[gw * 32 + lane];
    float4 bl = ((const float4*)b_loop)[lane];
    xl.x += bl.x; xl.y += bl.y; xl.z += bl.z; xl.w += bl.w;
    float4 wg = ((const float4*)Wg_loop)[lane];
    float s = warp_sum(xl.x * wg.x + xl.y * wg.y + xl.z * wg.z + xl.w * wg.w);
    float gate = sigmoidf_(s + bg_loop[0]);
    float4 o = make_float4(xl.x * gate, xl.y * gate, xl.z * gate, xl.w * gate);
    ((float4*)g_acc)[gw * 32 + lane] = o;

    float4 hi = ((const float4*)g_hin)[gw * 32 + lane];
    float4 wi = ((const float4*)Wg_in)[lane];
    float si = warp_sum(hi.x * wi.x + hi.y * wi.y + hi.z * wi.z + hi.w * wi.w);
    if (lane == 0) g_gate[0][gw] = si;

    float4 ho = ((const float4*)g_hout)[gw * 32 + lane];
    float4 wo = ((const float4*)Wg_out)[lane];
    float so = warp_sum(ho.x * wo.x + ho.y * wo.y + ho.z * wo.z + ho.w * wo.w);
    if (lane == 0) g_gate[1][gw] = so;
}

// ---------------- edge scatter: one warp per edge, int32 indices, clamped ----------------
__global__ void edge_kernel(int dir, const int* __restrict__ src,
                            const int* __restrict__ dst,
                            const int* __restrict__ lab,
                            const float* __restrict__ b_lab, int E, int N) {
    int gw = (int)((blockIdx.x * (unsigned)blockDim.x + threadIdx.x) >> 5);
    int lane = threadIdx.x & 31;
    if (gw >= E) return;

    int s = min(max(src[gw], 0), N - 1);
    int d = min(max(dst[gw], 0), N - 1);
    int l = min(max(lab[gw], 0), NLAB - 1);

    const float* h = dir ? g_hout : g_hin;
    float gate = sigmoidf_(g_gate[dir][s] + g_c[dir][l]);

    float4 m = ((const float4*)h)[s * 32 + lane];
    float4 bl = ((const float4*)b_lab)[l * 32 + lane];

    float* op = g_acc + (size_t)d * 128 + lane * 4;
    atomicAdd(op + 0, gate * (m.x + bl.x));
    atomicAdd(op + 1, gate * (m.y + bl.y));
    atomicAdd(op + 2, gate * (m.z + bl.z));
    atomicAdd(op + 3, gate * (m.w + bl.w));
}

// ---------------- final relu: g_acc -> d_out ----------------
__global__ void relu_kernel(float* __restrict__ out, int n4) {
    int i = blockIdx.x * blockDim.x + threadIdx.x;
    if (i < n4) {
        float4 v = ((const float4*)g_acc)[i];
        v.x = fmaxf(v.x, 0.f); v.y = fmaxf(v.y, 0.f);
        v.z = fmaxf(v.z, 0.f); v.w = fmaxf(v.w, 0.f);
        ((float4*)out)[i] = v;
    }
}

// ---------------- launch ----------------
extern "C" void kernel_launch(void* const* d_in, const int* in_sizes, int n_in,
                              void* d_out, int out_size) {
    const float* x        = (const float*)d_in[0];
    const int* ei         = (const int*)d_in[1];   // [2, E] delivered as int32
    const int* lab        = (const int*)d_in[2];   // [E] int32
    const float* W_loop   = (const float*)d_in[3];
    const float* b_loop   = (const float*)d_in[4];
    const float* Wg_loop  = (const float*)d_in[5];
    const float* bg_loop  = (const float*)d_in[6];
    const float* W_in     = (const float*)d_in[7];
    const float* blab_in  = (const float*)d_in[8];
    const float* Wg_in    = (const float*)d_in[9];
    const float* bg_in    = (const float*)d_in[10];
    const float* W_out    = (const float*)d_in[11];
    const float* blab_out = (const float*)d_in[12];
    const float* Wg_out   = (const float*)d_in[13];
    const float* bg_out   = (const float*)d_in[14];

    int N = in_sizes[0] / DIMS;
    int E = in_sizes[2];

    // prep (tiny)
    prep_w2_kernel<<<dim3(DIMS, 2), DIMS>>>(W_in, W_out);
    prep_c_kernel<<<1, 32>>>(Wg_in, blab_in, bg_in, Wg_out, blab_out, bg_out);

    // node GEMMs: [N,128] @ [128,128] for loop / in / out
    size_t smem = (size_t)(128 * 132 + 128 * 128) * sizeof(float);
    cudaFuncSetAttribute(gemm_kernel, cudaFuncAttributeMaxDynamicSharedMemorySize,
                         (int)smem);
    gemm_kernel<<<dim3((N + 127) / 128, 3), 256, smem>>>(x, W_loop, N);

    // node epilogue: writes xl into g_acc, per-node gate scalars
    node_post_kernel<<<(N + 7) / 8, 256>>>(b_loop, Wg_loop, bg_loop, Wg_in, Wg_out, N);

    // edge scatters (atomic add into g_acc)
    int eblocks = (int)(((long long)E * 32 + 255) / 256);
    // conv_in: messages from src (row 0) aggregated at dst (row 1)
    edge_kernel<<<eblocks, 256>>>(0, ei, ei + E, lab, blab_in, E, N);
    // conv_out: edge_index flipped -> src/dst roles swapped
    edge_kernel<<<eblocks, 256>>>(1, ei + E, ei, lab, blab_out, E, N);

    // final relu into d_out
    int n4 = N * DIMS / 4;
    relu_kernel<<<(n4 + 255) / 256, 256>>>((float*)d_out, n4);
}

// round 6
// speedup vs baseline: 1.6421x; 1.6421x over previous
#include <cuda_runtime.h>

#define DIMS 128
#define NLAB 5
#define MAXN 50000

// ---------------- device scratch (no allocations allowed) ----------------
__device__ float g_W2[2][DIMS * DIMS];      // W_in@W_in, W_out@W_out
__device__ float g_c[2][NLAB];              // per-label gate constants
__device__ float g_gate[2][MAXN];           // per-node h.Wg scalars
__device__ float g_hin[MAXN * DIMS];        // x @ (W_in @ W_in)
__device__ float g_hout[MAXN * DIMS];       // x @ (W_out @ W_out)
__device__ float g_acc[MAXN * DIMS];        // accumulator (xl + scatter sums)

__device__ __forceinline__ float sigmoidf_(float x) {
    return 1.0f / (1.0f + __expf(-x));
}

// ---------------- prep: W2 = W @ W (tiny) ----------------
__global__ void prep_w2_kernel(const float* __restrict__ Win,
                               const float* __restrict__ Wout) {
    __shared__ float wrow[DIMS];
    const float* W = (blockIdx.y == 0) ? Win : Wout;
    int r = blockIdx.x, c = threadIdx.x;
    wrow[c] = W[r * DIMS + c];
    __syncthreads();
    float s = 0.0f;
#pragma unroll 8
    for (int k = 0; k < DIMS; k++) s += wrow[k] * W[k * DIMS + c];
    g_W2[blockIdx.y][r * DIMS + c] = s;
}

// ---------------- prep: c[dir][lab] = b_lab[lab] . Wg + bg_lab[lab] ----------------
__global__ void prep_c_kernel(const float* __restrict__ Wg_in,
                              const float* __restrict__ blab_in,
                              const float* __restrict__ bg_in,
                              const float* __restrict__ Wg_out,
                              const float* __restrict__ blab_out,
                              const float* __restrict__ bg_out) {
    int t = threadIdx.x;
    if (t >= 2 * NLAB) return;
    int w = t / NLAB, l = t % NLAB;
    const float* Wg = w ? Wg_out : Wg_in;
    const float* bl = w ? blab_out : blab_in;
    const float* bg = w ? bg_out : bg_in;
    float s = bg[l];
    for (int d = 0; d < DIMS; d++) s += bl[l * DIMS + d] * Wg[d];
    g_c[w][l] = s;
}

// ---------------- SGEMM + fused epilogue ----------------
// blockIdx.y==0: g_acc = gate_loop(x@W_loop + b_loop)   (self-loop branch, fully fused)
// blockIdx.y==1: g_hin  = x@W2_in,  g_gate[0] = h.Wg_in
// blockIdx.y==2: g_hout = x@W2_out, g_gate[1] = h.Wg_out
__global__ __launch_bounds__(256) void gemm_kernel(const float* __restrict__ x,
                                                   const float* __restrict__ Wloop,
                                                   const float* __restrict__ b_loop,
                                                   const float* __restrict__ Wg_loop,
                                                   const float* __restrict__ bg_loop,
                                                   const float* __restrict__ Wg_in,
                                                   const float* __restrict__ Wg_out,
                                                   int M) {
    extern __shared__ float smem[];
    float* As = smem;                 // [128][132] padded rows
    float* Bs = smem + 128 * 132;     // [128][128]

    const float* W = (blockIdx.y == 0) ? Wloop : g_W2[blockIdx.y - 1];

    int tid = threadIdx.x;
    int m0 = blockIdx.x * 128;

    float4* Bs4 = (float4*)Bs;
    const float4* W4 = (const float4*)W;
#pragma unroll
    for (int i = 0; i < 16; i++) Bs4[i * 256 + tid] = W4[i * 256 + tid];

    float4* As4 = (float4*)As;
    const float4* x4 = (const float4*)x;
#pragma unroll
    for (int i = 0; i < 16; i++) {
        int fidx = tid + i * 256;
        int m = fidx >> 5, kq = fidx & 31;
        float4 v = make_float4(0.f, 0.f, 0.f, 0.f);
        if (m0 + m < M) v = x4[(size_t)(m0 + m) * 32 + kq];
        As4[m * 33 + kq] = v;
    }
    __syncthreads();

    int tx = tid & 15, ty = tid >> 4;
    float acc[8][8];
#pragma unroll
    for (int i = 0; i < 8; i++)
#pragma unroll
        for (int j = 0; j < 8; j++) acc[i][j] = 0.0f;

    const float* arow = As + (ty * 8) * 132;
#pragma unroll 2
    for (int k = 0; k < 128; k++) {
        float a[8];
#pragma unroll
        for (int i = 0; i < 8; i++) a[i] = arow[i * 132 + k];
        float4 b0 = Bs4[k * 32 + tx * 2];
        float4 b1 = Bs4[k * 32 + tx * 2 + 1];
        float b[8] = {b0.x, b0.y, b0.z, b0.w, b1.x, b1.y, b1.z, b1.w};
#pragma unroll
        for (int i = 0; i < 8; i++)
#pragma unroll
            for (int j = 0; j < 8; j++) acc[i][j] += a[i] * b[j];
    }

    // ---- fused epilogue ----
    if (blockIdx.y == 0) {
        // self-loop branch: add bias, per-row gate dot, gated write to g_acc
        float4 bA = ((const float4*)b_loop)[tx * 2];
        float4 bB = ((const float4*)b_loop)[tx * 2 + 1];
        float4 wA = ((const float4*)Wg_loop)[tx * 2];
        float4 wB = ((const float4*)Wg_loop)[tx * 2 + 1];
        float bgv = bg_loop[0];
#pragma unroll
        for (int i = 0; i < 8; i++) {
            float v[8];
            v[0] = acc[i][0] + bA.x; v[1] = acc[i][1] + bA.y;
            v[2] = acc[i][2] + bA.z; v[3] = acc[i][3] + bA.w;
            v[4] = acc[i][4] + bB.x; v[5] = acc[i][5] + bB.y;
            v[6] = acc[i][6] + bB.z; v[7] = acc[i][7] + bB.w;
            float p = v[0] * wA.x + v[1] * wA.y + v[2] * wA.z + v[3] * wA.w
                    + v[4] * wB.x + v[5] * wB.y + v[6] * wB.z + v[7] * wB.w;
#pragma unroll
            for (int o = 1; o < 16; o <<= 1) p += __shfl_xor_sync(0xffffffffu, p, o);
            float gate = sigmoidf_(p + bgv);
            int row = m0 + ty * 8 + i;
            if (row < M) {
                float4* o4 = (float4*)(g_acc + (size_t)row * 128 + tx * 8);
                o4[0] = make_float4(gate * v[0], gate * v[1], gate * v[2], gate * v[3]);
                o4[1] = make_float4(gate * v[4], gate * v[5], gate * v[6], gate * v[7]);
            }
        }
    } else {
        int dir = blockIdx.y - 1;
        const float* Wg = dir ? Wg_out : Wg_in;
        float* outp = dir ? g_hout : g_hin;
        float4 wA = ((const float4*)Wg)[tx * 2];
        float4 wB = ((const float4*)Wg)[tx * 2 + 1];
#pragma unroll
        for (int i = 0; i < 8; i++) {
            float p = acc[i][0] * wA.x + acc[i][1] * wA.y + acc[i][2] * wA.z + acc[i][3] * wA.w
                    + acc[i][4] * wB.x + acc[i][5] * wB.y + acc[i][6] * wB.z + acc[i][7] * wB.w;
#pragma unroll
            for (int o = 1; o < 16; o <<= 1) p += __shfl_xor_sync(0xffffffffu, p, o);
            int row = m0 + ty * 8 + i;
            if (row < M) {
                float4* o4 = (float4*)(outp + (size_t)row * 128 + tx * 8);
                o4[0] = make_float4(acc[i][0], acc[i][1], acc[i][2], acc[i][3]);
                o4[1] = make_float4(acc[i][4], acc[i][5], acc[i][6], acc[i][7]);
                if (tx == 0) g_gate[dir][row] = p;
            }
        }
    }
}

// ---------------- fused edge scatter: one warp per edge, both directions, vec4 atomics ----------------
__global__ void edge_fused_kernel(const int* __restrict__ src,
                                  const int* __restrict__ dst,
                                  const int* __restrict__ lab,
                                  const float* __restrict__ blab_in,
                                  const float* __restrict__ blab_out,
                                  int E, int N) {
    int gw = (int)((blockIdx.x * (unsigned)blockDim.x + threadIdx.x) >> 5);
    int lane = threadIdx.x & 31;
    if (gw >= E) return;

    int s = min(max(src[gw], 0), N - 1);
    int d = min(max(dst[gw], 0), N - 1);
    int l = min(max(lab[gw], 0), NLAB - 1);

    // conv_in: message h_in[s] -> acc[d];  conv_out: message h_out[d] -> acc[s]
    float gi = sigmoidf_(g_gate[0][s] + g_c[0][l]);
    float go = sigmoidf_(g_gate[1][d] + g_c[1][l]);

    float4 mi = ((const float4*)g_hin)[(size_t)s * 32 + lane];
    float4 bi = ((const float4*)blab_in)[l * 32 + lane];
    float4 mo = ((const float4*)g_hout)[(size_t)d * 32 + lane];
    float4 bo = ((const float4*)blab_out)[l * 32 + lane];

    float4 vi = make_float4(gi * (mi.x + bi.x), gi * (mi.y + bi.y),
                            gi * (mi.z + bi.z), gi * (mi.w + bi.w));
    float4 vo = make_float4(go * (mo.x + bo.x), go * (mo.y + bo.y),
                            go * (mo.z + bo.z), go * (mo.w + bo.w));

    atomicAdd(((float4*)g_acc) + (size_t)d * 32 + lane, vi);
    atomicAdd(((float4*)g_acc) + (size_t)s * 32 + lane, vo);
}

// ---------------- final relu: g_acc -> d_out ----------------
__global__ void relu_kernel(float* __restrict__ out, int n4) {
    int i = blockIdx.x * blockDim.x + threadIdx.x;
    if (i < n4) {
        float4 v = ((const float4*)g_acc)[i];
        v.x = fmaxf(v.x, 0.f); v.y = fmaxf(v.y, 0.f);
        v.z = fmaxf(v.z, 0.f); v.w = fmaxf(v.w, 0.f);
        ((float4*)out)[i] = v;
    }
}

// ---------------- launch ----------------
extern "C" void kernel_launch(void* const* d_in, const int* in_sizes, int n_in,
                              void* d_out, int out_size) {
    const float* x        = (const float*)d_in[0];
    const int* ei         = (const int*)d_in[1];   // [2, E] delivered as int32
    const int* lab        = (const int*)d_in[2];   // [E] int32
    const float* W_loop   = (const float*)d_in[3];
    const float* b_loop   = (const float*)d_in[4];
    const float* Wg_loop  = (const float*)d_in[5];
    const float* bg_loop  = (const float*)d_in[6];
    const float* W_in     = (const float*)d_in[7];
    const float* blab_in  = (const float*)d_in[8];
    const float* Wg_in    = (const float*)d_in[9];
    const float* bg_in    = (const float*)d_in[10];
    const float* W_out    = (const float*)d_in[11];
    const float* blab_out = (const float*)d_in[12];
    const float* Wg_out   = (const float*)d_in[13];
    const float* bg_out   = (const float*)d_in[14];

    int N = in_sizes[0] / DIMS;
    int E = in_sizes[2];

    // prep (tiny)
    prep_w2_kernel<<<dim3(DIMS, 2), DIMS>>>(W_in, W_out);
    prep_c_kernel<<<1, 32>>>(Wg_in, blab_in, bg_in, Wg_out, blab_out, bg_out);

    // node GEMMs + fused epilogues
    size_t smem = (size_t)(128 * 132 + 128 * 128) * sizeof(float);
    cudaFuncSetAttribute(gemm_kernel, cudaFuncAttributeMaxDynamicSharedMemorySize,
                         (int)smem);
    gemm_kernel<<<dim3((N + 127) / 128, 3), 256, smem>>>(
        x, W_loop, b_loop, Wg_loop, bg_loop, Wg_in, Wg_out, N);

    // fused edge scatter, both directions, vec4 atomics into g_acc
    int eblocks = (int)(((long long)E * 32 + 255) / 256);
    edge_fused_kernel<<<eblocks, 256>>>(ei, ei + E, lab, blab_in, blab_out, E, N);

    // final relu into d_out
    int n4 = N * DIMS / 4;
    relu_kernel<<<(n4 + 255) / 256, 256>>>((float*)d_out, n4);
}

// round 10
// speedup vs baseline: 1.8634x; 1.1348x over previous
#include <cuda_runtime.h>
#include <cstdint>

#define DIMS 128
#define NLAB 5
#define MAXN 50000

// ---------------- device scratch ----------------
__device__ float g_W2[2][DIMS * DIMS];        // W_in@W_in, W_out@W_out (fp32)
__device__ float g_c[2][NLAB];                // per-label gate constants
__device__ float g_gate[2][MAXN];             // per-node h.Wg scalars
__device__ float g_hin[MAXN * DIMS];          // x @ (W_in @ W_in)
__device__ float g_hout[MAXN * DIMS];         // x @ (W_out @ W_out)
__device__ float g_acc[MAXN * DIMS];          // accumulator (xl + scatter sums)

__device__ __forceinline__ float sigmoidf_(float x) {
    return 1.0f / (1.0f + __expf(-x));
}

__device__ __forceinline__ float tf32r(float x) {
    uint32_t u;
    asm("cvt.rna.tf32.f32 %0, %1;" : "=r"(u) : "f"(x));
    return __uint_as_float(u);
}

__device__ __forceinline__ void mma_tf32(float* c, uint32_t a0, uint32_t a1,
                                         uint32_t a2, uint32_t a3,
                                         uint32_t b0, uint32_t b1) {
    asm volatile(
        "mma.sync.aligned.m16n8k8.row.col.f32.tf32.tf32.f32 "
        "{%0,%1,%2,%3}, {%4,%5,%6,%7}, {%8,%9}, {%0,%1,%2,%3};"
        : "+f"(c[0]), "+f"(c[1]), "+f"(c[2]), "+f"(c[3])
        : "r"(a0), "r"(a1), "r"(a2), "r"(a3), "r"(b0), "r"(b1));
}

// ---------------- prep: W2 = W @ W ----------------
__global__ void prep_w2_kernel(const float* __restrict__ Win,
                               const float* __restrict__ Wout) {
    __shared__ float wrow[DIMS];
    const float* W = (blockIdx.y == 0) ? Win : Wout;
    int r = blockIdx.x, c = threadIdx.x;
    wrow[c] = W[r * DIMS + c];
    __syncthreads();
    float s = 0.0f;
#pragma unroll 8
    for (int k = 0; k < DIMS; k++) s += wrow[k] * W[k * DIMS + c];
    g_W2[blockIdx.y][r * DIMS + c] = s;
}

// ---------------- prep: gate constants ----------------
__global__ void prep_c_kernel(const float* __restrict__ Wg_in,
                              const float* __restrict__ blab_in,
                              const float* __restrict__ bg_in,
                              const float* __restrict__ Wg_out,
                              const float* __restrict__ blab_out,
                              const float* __restrict__ bg_out) {
    int t = threadIdx.x;
    if (t >= 2 * NLAB) return;
    int w = t / NLAB, l = t % NLAB;
    const float* Wg = w ? Wg_out : Wg_in;
    const float* bl = w ? blab_out : blab_in;
    const float* bg = w ? bg_out : bg_in;
    float s = bg[l];
    for (int d = 0; d < DIMS; d++) s += bl[l * DIMS + d] * Wg[d];
    g_c[w][l] = s;
}

// ---------------- mma.sync tf32 GEMM (3-pass split) + fused epilogue ----------------
// blockIdx.y==0: g_acc = gate_loop(x@W_loop + b_loop)
// blockIdx.y==1: g_hin  = x@W2_in,  g_gate[0] = h.Wg_in
// blockIdx.y==2: g_hout = x@W2_out, g_gate[1] = h.Wg_out
//
// smem: As fp32 [128][136]; Wh/Wl tf32 [128][136] (B^T, paired (k,k+4) layout)
#define AS_STRIDE 136
#define SMEM_AS 0
#define SMEM_WH (128 * AS_STRIDE)
#define SMEM_WL (2 * 128 * AS_STRIDE)
#define GEMM_SMEM (3 * 128 * AS_STRIDE * 4)

__global__ __launch_bounds__(256) void gemm_mma_kernel(const float* __restrict__ x,
                                                       const float* __restrict__ Wloop,
                                                       const float* __restrict__ b_loop,
                                                       const float* __restrict__ Wg_loop,
                                                       const float* __restrict__ bg_loop,
                                                       const float* __restrict__ Wg_in,
                                                       const float* __restrict__ Wg_out,
                                                       int M) {
    extern __shared__ float smem[];
    float* As = smem + SMEM_AS;
    float* Wh = smem + SMEM_WH;
    float* Wl = smem + SMEM_WL;

    const float* W = (blockIdx.y == 0) ? Wloop : g_W2[blockIdx.y - 1];

    int tid = threadIdx.x;
    int wid = tid >> 5, lane = tid & 31;
    int g = lane >> 2, t4 = lane & 3;
    int m0 = blockIdx.x * 128;

    // ---- load W, transpose + tf32 split into paired layout ----
    // For B^T row n: position ks*8 + (kk&3)*2 + (kk>>2) holds k = ks*8+kk
    for (int idx = tid; idx < DIMS * DIMS; idx += 256) {
        int k = idx >> 7, n = idx & 127;
        float v = W[idx];                 // W[k*128 + n], coalesced
        float hi = tf32r(v);
        float lo = tf32r(v - hi);
        int ks = k >> 3, kk = k & 7;
        int pos = ks * 8 + (kk & 3) * 2 + (kk >> 2);
        Wh[n * AS_STRIDE + pos] = hi;
        Wl[n * AS_STRIDE + pos] = lo;
    }

    // ---- load x tile (fp32) ----
    const float4* x4 = (const float4*)x;
#pragma unroll
    for (int i = 0; i < 16; i++) {
        int fidx = tid + i * 256;
        int r = fidx >> 5, kq = fidx & 31;
        float4 v = make_float4(0.f, 0.f, 0.f, 0.f);
        if (m0 + r < M) v = x4[(size_t)(m0 + r) * 32 + kq];
        *(float4*)&As[r * AS_STRIDE + kq * 4] = v;
    }
    __syncthreads();

    // ---- mainloop: warp tile 16 rows x 128 cols ----
    int m0w = wid * 16;
    const float* pa0 = As + (m0w + g) * AS_STRIDE;
    const float* pa1 = As + (m0w + g + 8) * AS_STRIDE;

    float acc[16][4];
#pragma unroll
    for (int j = 0; j < 16; j++)
#pragma unroll
        for (int q = 0; q < 4; q++) acc[j][q] = 0.0f;

#pragma unroll 4
    for (int ks = 0; ks < 16; ks++) {
        int k0 = ks * 8;
        float f0 = pa0[k0 + t4], f1 = pa1[k0 + t4];
        float f2 = pa0[k0 + t4 + 4], f3 = pa1[k0 + t4 + 4];
        uint32_t ah0 = __float_as_uint(tf32r(f0));
        uint32_t ah1 = __float_as_uint(tf32r(f1));
        uint32_t ah2 = __float_as_uint(tf32r(f2));
        uint32_t ah3 = __float_as_uint(tf32r(f3));
        uint32_t al0 = __float_as_uint(tf32r(f0 - __uint_as_float(ah0)));
        uint32_t al1 = __float_as_uint(tf32r(f1 - __uint_as_float(ah1)));
        uint32_t al2 = __float_as_uint(tf32r(f2 - __uint_as_float(ah2)));
        uint32_t al3 = __float_as_uint(tf32r(f3 - __uint_as_float(ah3)));
#pragma unroll
        for (int j = 0; j < 16; j++) {
            int boff = (j * 8 + g) * AS_STRIDE + k0 + t4 * 2;
            float2 bh = *(const float2*)&Wh[boff];
            float2 bl = *(const float2*)&Wl[boff];
            uint32_t bh0 = __float_as_uint(bh.x), bh1 = __float_as_uint(bh.y);
            uint32_t bl0 = __float_as_uint(bl.x), bl1 = __float_as_uint(bl.y);
            mma_tf32(acc[j], ah0, ah1, ah2, ah3, bh0, bh1);   // Ah*Bh
            mma_tf32(acc[j], al0, al1, al2, al3, bh0, bh1);   // Al*Bh
            mma_tf32(acc[j], ah0, ah1, ah2, ah3, bl0, bl1);   // Ah*Bl
        }
    }

    // ---- epilogue ----
    // thread owns rows r0 = m0+m0w+g, r1 = r0+8; cols j*8 + t4*2 (+1)
    int r0 = m0 + m0w + g;
    int r1 = r0 + 8;

    if (blockIdx.y == 0) {
        float p0 = 0.f, p1 = 0.f;
#pragma unroll
        for (int j = 0; j < 16; j++) {
            int c0 = j * 8 + t4 * 2;
            float2 bl2 = *(const float2*)&b_loop[c0];
            float2 wg2 = *(const float2*)&Wg_loop[c0];
            acc[j][0] += bl2.x; acc[j][1] += bl2.y;
            acc[j][2] += bl2.x; acc[j][3] += bl2.y;
            p0 += acc[j][0] * wg2.x + acc[j][1] * wg2.y;
            p1 += acc[j][2] * wg2.x + acc[j][3] * wg2.y;
        }
        p0 += __shfl_xor_sync(0xffffffffu, p0, 1);
        p0 += __shfl_xor_sync(0xffffffffu, p0, 2);
        p1 += __shfl_xor_sync(0xffffffffu, p1, 1);
        p1 += __shfl_xor_sync(0xffffffffu, p1, 2);
        float bgv = __ldg(&bg_loop[0]);
        float g0 = sigmoidf_(p0 + bgv);
        float g1 = sigmoidf_(p1 + bgv);
#pragma unroll
        for (int j = 0; j < 16; j++) {
            int c0 = j * 8 + t4 * 2;
            if (r0 < M)
                *(float2*)&g_acc[(size_t)r0 * 128 + c0] = make_float2(g0 * acc[j][0], g0 * acc[j][1]);
            if (r1 < M)
                *(float2*)&g_acc[(size_t)r1 * 128 + c0] = make_float2(g1 * acc[j][2], g1 * acc[j][3]);
        }
    } else {
        int dir = blockIdx.y - 1;
        const float* Wg = dir ? Wg_out : Wg_in;
        float* outp = dir ? g_hout : g_hin;
        float p0 = 0.f, p1 = 0.f;
#pragma unroll
        for (int j = 0; j < 16; j++) {
            int c0 = j * 8 + t4 * 2;
            float2 wg2 = *(const float2*)&Wg[c0];
            p0 += acc[j][0] * wg2.x + acc[j][1] * wg2.y;
            p1 += acc[j][2] * wg2.x + acc[j][3] * wg2.y;
            if (r0 < M)
                *(float2*)&outp[(size_t)r0 * 128 + c0] = make_float2(acc[j][0], acc[j][1]);
            if (r1 < M)
                *(float2*)&outp[(size_t)r1 * 128 + c0] = make_float2(acc[j][2], acc[j][3]);
        }
        p0 += __shfl_xor_sync(0xffffffffu, p0, 1);
        p0 += __shfl_xor_sync(0xffffffffu, p0, 2);
        p1 += __shfl_xor_sync(0xffffffffu, p1, 1);
        p1 += __shfl_xor_sync(0xffffffffu, p1, 2);
        if (t4 == 0) {
            if (r0 < M) g_gate[dir][r0] = p0;
            if (r1 < M) g_gate[dir][r1] = p1;
        }
    }
}

// ---------------- fused edge scatter: 2 edges per warp, vec4 atomics ----------------
__global__ void edge_fused_kernel(const int* __restrict__ src,
                                  const int* __restrict__ dst,
                                  const int* __restrict__ lab,
                                  const float* __restrict__ blab_in,
                                  const float* __restrict__ blab_out,
                                  int E, int N) {
    int gw = (int)((blockIdx.x * (unsigned)blockDim.x + threadIdx.x) >> 5);
    int lane = threadIdx.x & 31;
    int e0 = gw * 2;
    if (e0 >= E) return;
    int e1 = e0 + 1;
    bool do1 = (e1 < E);
    if (!do1) e1 = e0;

    int s0 = min(max(src[e0], 0), N - 1), d0 = min(max(dst[e0], 0), N - 1);
    int l0 = min(max(lab[e0], 0), NLAB - 1);
    int s1 = min(max(src[e1], 0), N - 1), d1 = min(max(dst[e1], 0), N - 1);
    int l1 = min(max(lab[e1], 0), NLAB - 1);

    float gi0 = sigmoidf_(g_gate[0][s0] + g_c[0][l0]);
    float go0 = sigmoidf_(g_gate[1][d0] + g_c[1][l0]);
    float gi1 = sigmoidf_(g_gate[0][s1] + g_c[0][l1]);
    float go1 = sigmoidf_(g_gate[1][d1] + g_c[1][l1]);

    float4 mi0 = ((const float4*)g_hin)[(size_t)s0 * 32 + lane];
    float4 mo0 = ((const float4*)g_hout)[(size_t)d0 * 32 + lane];
    float4 mi1 = ((const float4*)g_hin)[(size_t)s1 * 32 + lane];
    float4 mo1 = ((const float4*)g_hout)[(size_t)d1 * 32 + lane];

    float4 bi0 = ((const float4*)blab_in)[l0 * 32 + lane];
    float4 bo0 = ((const float4*)blab_out)[l0 * 32 + lane];
    float4 bi1 = ((const float4*)blab_in)[l1 * 32 + lane];
    float4 bo1 = ((const float4*)blab_out)[l1 * 32 + lane];

    float4 vi0 = make_float4(gi0 * (mi0.x + bi0.x), gi0 * (mi0.y + bi0.y),
                             gi0 * (mi0.z + bi0.z), gi0 * (mi0.w + bi0.w));
    float4 vo0 = make_float4(go0 * (mo0.x + bo0.x), go0 * (mo0.y + bo0.y),
                             go0 * (mo0.z + bo0.z), go0 * (mo0.w + bo0.w));
    atomicAdd(((float4*)g_acc) + (size_t)d0 * 32 + lane, vi0);
    atomicAdd(((float4*)g_acc) + (size_t)s0 * 32 + lane, vo0);

    if (do1) {
        float4 vi1 = make_float4(gi1 * (mi1.x + bi1.x), gi1 * (mi1.y + bi1.y),
                                 gi1 * (mi1.z + bi1.z), gi1 * (mi1.w + bi1.w));
        float4 vo1 = make_float4(go1 * (mo1.x + bo1.x), go1 * (mo1.y + bo1.y),
                                 go1 * (mo1.z + bo1.z), go1 * (mo1.w + bo1.w));
        atomicAdd(((float4*)g_acc) + (size_t)d1 * 32 + lane, vi1);
        atomicAdd(((float4*)g_acc) + (size_t)s1 * 32 + lane, vo1);
    }
}

// ---------------- final relu: g_acc -> d_out ----------------
__global__ void relu_kernel(float* __restrict__ out, int n4) {
    int i = blockIdx.x * blockDim.x + threadIdx.x;
    if (i < n4) {
        float4 v = ((const float4*)g_acc)[i];
        v.x = fmaxf(v.x, 0.f); v.y = fmaxf(v.y, 0.f);
        v.z = fmaxf(v.z, 0.f); v.w = fmaxf(v.w, 0.f);
        ((float4*)out)[i] = v;
    }
}

// ---------------- launch ----------------
extern "C" void kernel_launch(void* const* d_in, const int* in_sizes, int n_in,
                              void* d_out, int out_size) {
    const float* x        = (const float*)d_in[0];
    const int* ei         = (const int*)d_in[1];   // [2, E] int32
    const int* lab        = (const int*)d_in[2];   // [E] int32
    const float* W_loop   = (const float*)d_in[3];
    const float* b_loop   = (const float*)d_in[4];
    const float* Wg_loop  = (const float*)d_in[5];
    const float* bg_loop  = (const float*)d_in[6];
    const float* W_in     = (const float*)d_in[7];
    const float* blab_in  = (const float*)d_in[8];
    const float* Wg_in    = (const float*)d_in[9];
    const float* bg_in    = (const float*)d_in[10];
    const float* W_out    = (const float*)d_in[11];
    const float* blab_out = (const float*)d_in[12];
    const float* Wg_out   = (const float*)d_in[13];
    const float* bg_out   = (const float*)d_in[14];

    int N = in_sizes[0] / DIMS;
    int E = in_sizes[2];

    prep_w2_kernel<<<dim3(DIMS, 2), DIMS>>>(W_in, W_out);
    prep_c_kernel<<<1, 32>>>(Wg_in, blab_in, bg_in, Wg_out, blab_out, bg_out);

    cudaFuncSetAttribute(gemm_mma_kernel, cudaFuncAttributeMaxDynamicSharedMemorySize,
                         GEMM_SMEM);
    gemm_mma_kernel<<<dim3((N + 127) / 128, 3), 256, GEMM_SMEM>>>(
        x, W_loop, b_loop, Wg_loop, bg_loop, Wg_in, Wg_out, N);

    int warps = (E + 1) / 2;
    int eblocks = (warps + 7) / 8;
    edge_fused_kernel<<<eblocks, 256>>>(ei, ei + E, lab, blab_in, blab_out, E, N);

    int n4 = N * DIMS / 4;
    relu_kernel<<<(n4 + 255) / 256, 256>>>((float*)d_out, n4);
}